// round 8
// baseline (speedup 1.0000x reference)
#include <cuda_runtime.h>
#include <cstdint>

#define S 512
#define Hd 256
#define Bb 4
#define TT 8
#define HC 16
#define NCHUNK (Hd / HC)   // 16

// Scratch (no cudaMalloc allowed): 2MB + 2MB
__device__ float g_ht[Bb * S * Hd];        // [b][t][h], b_h folded in
__device__ float g_htpT[Bb * Hd * S];      // [b][h][t']  (transposed projection)

__device__ __forceinline__ float tanh_fast(float x) {
    float y;
    asm("tanh.approx.f32 %0, %1;" : "=f"(y) : "f"(x));
    return y;
}
__device__ __forceinline__ void cp16(uint32_t smem_dst, const void* gsrc) {
    asm volatile("cp.async.cg.shared.global [%0], [%1], 16;"
                 :: "r"(smem_dst), "l"(gsrc));
}
__device__ __forceinline__ void cp_commit() {
    asm volatile("cp.async.commit_group;");
}
template <int N>
__device__ __forceinline__ void cp_wait() {
    asm volatile("cp.async.wait_group %0;" :: "n"(N));
}

// ---------------------------------------------------------------------------
// K1: fused projection GEMM.  C[m][n] = sum_k h[m][k] * Wcat[k][n]
//   m in [0,2048) = b*512+t,  n in [0,512): n<256 -> W_t (ht out, +b_h),
//   n>=256 -> W_t_prime (htpT out, transposed store).
// ---------------------------------------------------------------------------
__global__ __launch_bounds__(256) void proj_kernel(
    const float* __restrict__ h, const float* __restrict__ Wt,
    const float* __restrict__ Wtp, const float* __restrict__ bh)
{
    __shared__ float As[64][17];
    __shared__ float Bs[16][64];

    const int tid = threadIdx.x;
    const int tx = tid & 15, ty = tid >> 4;
    const int m0 = blockIdx.x * 64;
    const int ny = blockIdx.y;
    const float* __restrict__ W = (ny < 4) ? Wt : Wtp;
    const int col0 = (ny & 3) * 64;

    const int lm  = tid >> 2;
    const int lk4 = (tid & 3) * 4;
    const int lbk = tid >> 6;
    const int lbn = tid & 63;

    float acc[4][4] = {};

    for (int k0 = 0; k0 < Hd; k0 += 16) {
        float4 av = *reinterpret_cast<const float4*>(
            &h[(size_t)(m0 + lm) * Hd + k0 + lk4]);
        As[lm][lk4 + 0] = av.x; As[lm][lk4 + 1] = av.y;
        As[lm][lk4 + 2] = av.z; As[lm][lk4 + 3] = av.w;
#pragma unroll
        for (int kk = 0; kk < 16; kk += 4)
            Bs[lbk + kk][lbn] = W[(size_t)(k0 + lbk + kk) * Hd + col0 + lbn];
        __syncthreads();
#pragma unroll
        for (int k = 0; k < 16; ++k) {
            float4 bv = *reinterpret_cast<const float4*>(&Bs[k][tx * 4]);
#pragma unroll
            for (int i = 0; i < 4; ++i) {
                float a = As[ty * 4 + i][k];
                acc[i][0] += a * bv.x; acc[i][1] += a * bv.y;
                acc[i][2] += a * bv.z; acc[i][3] += a * bv.w;
            }
        }
        __syncthreads();
    }

    const int m = m0 + ty * 4;
    const int n = col0 + tx * 4;
    if (ny < 4) {
        float4 bh4 = *reinterpret_cast<const float4*>(&bh[n]);
#pragma unroll
        for (int i = 0; i < 4; ++i) {
            float4 o = make_float4(acc[i][0] + bh4.x, acc[i][1] + bh4.y,
                                   acc[i][2] + bh4.z, acc[i][3] + bh4.w);
            *reinterpret_cast<float4*>(&g_ht[(size_t)(m + i) * Hd + n]) = o;
        }
    } else {
        const int b = m0 >> 9;
        const int t = m - b * S;
#pragma unroll
        for (int j = 0; j < 4; ++j)
#pragma unroll
            for (int i = 0; i < 4; ++i)
                g_htpT[((size_t)b * Hd + n + j) * S + t + i] = acc[i][j];
    }
}

// ---------------------------------------------------------------------------
// K2: scores (MUFU-bound, cp.async double-buffered) + sigmoid + softmax +
//     output matvec. One CTA per (b, 8-row t tile). 512 threads = t' column.
// ---------------------------------------------------------------------------
struct K2Smem {
    float ht[TT][Hd];            // 8KB
    float wa[Hd];                // 1KB
    float sums[TT][2];
    float w[TT][S];              // 16KB (exp / weights, never aliased)
    union {
        float  htp[2][HC][S];    // 64KB double-buffered htpT chunks
        float4 red[8][S];        // 64KB partial-output combine (htp dead)
    } u;
};

__global__ __launch_bounds__(512, 2) void attn_kernel(
    const float* __restrict__ h, const float* __restrict__ Wa,
    const float* __restrict__ ba, float* __restrict__ out)
{
    extern __shared__ char smem_raw[];
    K2Smem& sm = *reinterpret_cast<K2Smem*>(smem_raw);
    const int tid = threadIdx.x;
    const int b = blockIdx.x >> 6;
    const int t0 = (blockIdx.x & 63) * TT;

    const int crow = tid >> 7;          // 0..3   (chunk-load row base)
    const int ccol = (tid & 127) * 4;   // float4 column within t'

    // ---- prologue: async-stage ht tile + W_a + chunk0 (group 0), chunk1 (group 1)
    {
        const float* __restrict__ htg = &g_ht[((size_t)b * S + t0) * Hd];
        cp16((uint32_t)__cvta_generic_to_shared(&sm.ht[0][0]) + tid * 16,
             htg + tid * 4);                       // 512*16B = 8KB
        if (tid < 64)
            cp16((uint32_t)__cvta_generic_to_shared(&sm.wa[0]) + tid * 16,
                 Wa + tid * 4);
        const float* __restrict__ src = &g_htpT[(size_t)b * Hd * S];
        uint32_t dst0 = (uint32_t)__cvta_generic_to_shared(&sm.u.htp[0][0][0]);
#pragma unroll
        for (int r = 0; r < 4; ++r)
            cp16(dst0 + (uint32_t)(((crow + 4 * r) * S + ccol) * 4),
                 src + (size_t)(crow + 4 * r) * S + ccol);
        cp_commit();
        uint32_t dst1 = (uint32_t)__cvta_generic_to_shared(&sm.u.htp[1][0][0]);
#pragma unroll
        for (int r = 0; r < 4; ++r)
            cp16(dst1 + (uint32_t)(((crow + 4 * r) * S + ccol) * 4),
                 src + (size_t)(HC + crow + 4 * r) * S + ccol);
        cp_commit();
    }

    // ---- score phase ----
    float acc[TT] = {};
    for (int c = 0; c < NCHUNK; ++c) {
        if (c < NCHUNK - 1) cp_wait<1>(); else cp_wait<0>();
        __syncthreads();
        const int bufi = c & 1;
        const int h0 = c * HC;
#pragma unroll 4
        for (int j = 0; j < HC; ++j) {
            float hv = sm.u.htp[bufi][j][tid];
            float waj = sm.wa[h0 + j];
#pragma unroll
            for (int t = 0; t < TT; ++t)
                acc[t] += waj * tanh_fast(sm.ht[t][h0 + j] + hv);
        }
        __syncthreads();   // everyone done reading buf[c&1]
        if (c + 2 < NCHUNK) {
            const float* __restrict__ src =
                &g_htpT[((size_t)b * Hd + (c + 2) * HC) * S];
            uint32_t dst =
                (uint32_t)__cvta_generic_to_shared(&sm.u.htp[bufi][0][0]);
#pragma unroll
            for (int r = 0; r < 4; ++r)
                cp16(dst + (uint32_t)(((crow + 4 * r) * S + ccol) * 4),
                     src + (size_t)(crow + 4 * r) * S + ccol);
            cp_commit();
        }
    }

    // ---- sigmoid + exp ----
    const float ba_v = ba[0];
    float e[TT];
#pragma unroll
    for (int t = 0; t < TT; ++t) {
        float x = acc[t] + ba_v;
        float sg = 0.5f * tanh_fast(0.5f * x) + 0.5f;   // sigmoid via HW tanh
        e[t] = __expf(sg);                               // sg in (0,1): no max-sub
        sm.w[t][tid] = e[t];
    }
    __syncthreads();

    // ---- per-t row sums: all 16 warps (2 warps per row, half each) ----
    const int warp = tid >> 5, lane = tid & 31;
    {
        const int row = warp >> 1;
        const int half = (warp & 1) * 256;
        float s = 0.f;
#pragma unroll
        for (int i = 0; i < 256; i += 32) s += sm.w[row][half + i + lane];
#pragma unroll
        for (int o = 16; o > 0; o >>= 1) s += __shfl_xor_sync(0xffffffffu, s, o);
        if (lane == 0) sm.sums[row][warp & 1] = s;
    }
    __syncthreads();

    // ---- normalize, write attention weights ----
    float* __restrict__ wout = out + (size_t)Bb * S * Hd;
#pragma unroll
    for (int t = 0; t < TT; ++t) {
        float wv = e[t] / (sm.sums[t][0] + sm.sums[t][1]);
        sm.w[t][tid] = wv;
        wout[((size_t)b * S + t0 + t) * S + tid] = wv;
    }
    __syncthreads();

    // ---- output matvec: out[t][:] = sum_tp w[t][tp] * h[b][tp][:] ----
    const int g = tid >> 6, hq = tid & 63;
    const float4* __restrict__ h4 = reinterpret_cast<const float4*>(h);
    float4 o[TT];
#pragma unroll
    for (int t = 0; t < TT; ++t) o[t] = make_float4(0.f, 0.f, 0.f, 0.f);
    const int tp0 = g * 64;
#pragma unroll 4
    for (int it = 0; it < 64; ++it) {
        const int tp = tp0 + it;
        float4 v = h4[((size_t)b * S + tp) * (Hd / 4) + hq];
#pragma unroll
        for (int t = 0; t < TT; ++t) {
            float wv = sm.w[t][tp];
            o[t].x += wv * v.x; o[t].y += wv * v.y;
            o[t].z += wv * v.z; o[t].w += wv * v.w;
        }
    }
#pragma unroll
    for (int t = 0; t < TT; ++t) sm.u.red[g][t * 64 + hq] = o[t];
    __syncthreads();
    float4 r = make_float4(0.f, 0.f, 0.f, 0.f);
#pragma unroll
    for (int gg = 0; gg < 8; ++gg) {
        float4 p = sm.u.red[gg][tid];
        r.x += p.x; r.y += p.y; r.z += p.z; r.w += p.w;
    }
    const int tt = tid >> 6, hh = tid & 63;
    reinterpret_cast<float4*>(out)[((size_t)b * S + t0 + tt) * (Hd / 4) + hh] = r;
}

// ---------------------------------------------------------------------------
extern "C" void kernel_launch(void* const* d_in, const int* in_sizes, int n_in,
                              void* d_out, int out_size) {
    (void)in_sizes; (void)n_in; (void)out_size;
    const float* h   = (const float*)d_in[0];
    const float* Wt  = (const float*)d_in[1];
    const float* Wtp = (const float*)d_in[2];
    const float* bh  = (const float*)d_in[3];
    const float* Wa  = (const float*)d_in[4];
    const float* ba  = (const float*)d_in[5];
    float* out = (float*)d_out;

    cudaFuncSetAttribute(attn_kernel,
                         cudaFuncAttributeMaxDynamicSharedMemorySize,
                         (int)sizeof(K2Smem));

    dim3 g1(32, 8);
    proj_kernel<<<g1, 256>>>(h, Wt, Wtp, bh);
    attn_kernel<<<Bb * (S / TT), 512, sizeof(K2Smem)>>>(h, Wa, ba, out);
}